// round 1
// baseline (speedup 1.0000x reference)
#include <cuda_runtime.h>
#include <cuda_bf16.h>
#include <math.h>

// Problem constants
#define T_TOK 4096      // B*S
#define BATCH 2
#define SEQ   2048
#define NHEAD 32
#define HDIM  64
#define HID   2048      // NHEAD*HDIM
#define QKV_N 2176      // (H + 2*HKV) * D
#define ROPE_HALF 32

// ---------------- scratch (device globals; no allocation allowed) ----------
__device__ float g_qkv [T_TOK * QKV_N];   // qkv projection output
__device__ float g_q   [T_TOK * HID];     // q after rope: [T][H][D]
__device__ float g_k   [T_TOK * HDIM];    // k after rope: [T][D]
__device__ float g_v   [T_TOK * HDIM];    // v:            [T][D]
__device__ float g_attn[T_TOK * HID];     // attention out [T][H*D]

// ---------------------------------------------------------------------------
// Classic SGEMM, C[m][n] = sum_k A[m][k] * B[n][k]   (NT, both K-contiguous)
// BM=BN=128, BK=8, 256 threads, 8x8 per thread. Dims must be multiples.
// ---------------------------------------------------------------------------
__global__ __launch_bounds__(256) void sgemm_nt_kernel(
    const float* __restrict__ A, const float* __restrict__ B,
    float* __restrict__ C, int M, int N, int K)
{
    __shared__ float As[8][128];
    __shared__ float Bs[8][128];

    const int tid  = threadIdx.x;
    const int bm   = blockIdx.y * 128;
    const int bn   = blockIdx.x * 128;
    const int lrow = tid >> 1;          // 0..127
    const int lcol = (tid & 1) << 2;    // 0 or 4
    const int trow = (tid >> 4) << 3;   // 0..120
    const int tcol = (tid & 15) << 3;   // 0..120

    const float* Aptr = A + (size_t)(bm + lrow) * K + lcol;
    const float* Bptr = B + (size_t)(bn + lrow) * K + lcol;

    float acc[8][8];
    #pragma unroll
    for (int i = 0; i < 8; i++)
        #pragma unroll
        for (int j = 0; j < 8; j++) acc[i][j] = 0.f;

    for (int k0 = 0; k0 < K; k0 += 8) {
        float4 a4 = *(const float4*)(Aptr + k0);
        float4 b4 = *(const float4*)(Bptr + k0);
        As[lcol + 0][lrow] = a4.x; As[lcol + 1][lrow] = a4.y;
        As[lcol + 2][lrow] = a4.z; As[lcol + 3][lrow] = a4.w;
        Bs[lcol + 0][lrow] = b4.x; Bs[lcol + 1][lrow] = b4.y;
        Bs[lcol + 2][lrow] = b4.z; Bs[lcol + 3][lrow] = b4.w;
        __syncthreads();

        #pragma unroll
        for (int k = 0; k < 8; k++) {
            float rm[8], rn[8];
            #pragma unroll
            for (int i = 0; i < 8; i++) rm[i] = As[k][trow + i];
            #pragma unroll
            for (int j = 0; j < 8; j++) rn[j] = Bs[k][tcol + j];
            #pragma unroll
            for (int i = 0; i < 8; i++)
                #pragma unroll
                for (int j = 0; j < 8; j++)
                    acc[i][j] = fmaf(rm[i], rn[j], acc[i][j]);
        }
        __syncthreads();
    }

    float* Cp = C + (size_t)(bm + trow) * N + bn + tcol;
    #pragma unroll
    for (int i = 0; i < 8; i++) {
        #pragma unroll
        for (int j4 = 0; j4 < 2; j4++) {
            float4 o;
            o.x = acc[i][j4 * 4 + 0]; o.y = acc[i][j4 * 4 + 1];
            o.z = acc[i][j4 * 4 + 2]; o.w = acc[i][j4 * 4 + 3];
            *(float4*)(Cp + (size_t)i * N + j4 * 4) = o;
        }
    }
}

// ---------------------------------------------------------------------------
// RoPE + split: qkv [T][2176] -> g_q [T][H][D] (roped), g_k [T][D] (roped),
// g_v [T][D]. cos/sin: [T][32].
// ---------------------------------------------------------------------------
__global__ __launch_bounds__(256) void rope_split_kernel(
    const float* __restrict__ qkv,
    const float* __restrict__ cosb, const float* __restrict__ sinb,
    float* __restrict__ q, float* __restrict__ k, float* __restrict__ v)
{
    const int t = blockIdx.x;
    const float* row = qkv + (size_t)t * QKV_N;
    const float* cs  = cosb + t * ROPE_HALF;
    const float* sn  = sinb + t * ROPE_HALF;

    // q: 32 heads x 32 rotation pairs
    for (int i = threadIdx.x; i < NHEAD * ROPE_HALF; i += blockDim.x) {
        int hh = i >> 5, d = i & 31;
        float c = cs[d], s = sn[d];
        float x1 = row[hh * HDIM + d];
        float x2 = row[hh * HDIM + d + ROPE_HALF];
        q[(size_t)t * HID + hh * HDIM + d]             = x1 * c - x2 * s;
        q[(size_t)t * HID + hh * HDIM + d + ROPE_HALF] = x2 * c + x1 * s;
    }
    // k: 32 pairs
    for (int i = threadIdx.x; i < ROPE_HALF; i += blockDim.x) {
        float c = cs[i], s = sn[i];
        float x1 = row[HID + i];
        float x2 = row[HID + i + ROPE_HALF];
        k[(size_t)t * HDIM + i]             = x1 * c - x2 * s;
        k[(size_t)t * HDIM + i + ROPE_HALF] = x2 * c + x1 * s;
    }
    // v: copy 64
    for (int i = threadIdx.x; i < HDIM; i += blockDim.x) {
        v[(size_t)t * HDIM + i] = row[HID + HDIM + i];
    }
}

// ---------------------------------------------------------------------------
// Causal flash attention, GQA with 1 KV head.
// grid = (S/64, NHEAD, BATCH), block = 256 (16x16 threads, 4x4 per thread).
// ---------------------------------------------------------------------------
__global__ __launch_bounds__(256) void flash_attn_kernel(
    const float* __restrict__ Q, const float* __restrict__ Kg,
    const float* __restrict__ Vg, float* __restrict__ O)
{
    extern __shared__ float sm[];
    float* Qs = sm;                 // 64*64
    float* Ks = Qs + 64 * 64;       // 64*65 (padded)
    float* Vs = Ks + 64 * 65;       // 64*64
    float* Ps = Vs + 64 * 64;       // 64*64

    const int tid = threadIdx.x;
    const int tx = tid & 15;
    const int ty = tid >> 4;
    const int qt = blockIdx.x;      // query tile
    const int h  = blockIdx.y;
    const int b  = blockIdx.z;
    const float scale = 0.125f;     // 64^-0.5

    // load Q tile (rows qt*64 .. +63 of this head)
    for (int i = tid; i < 64 * 64; i += 256) {
        int r = i >> 6, c = i & 63;
        Qs[r * 64 + c] = Q[(((size_t)b * SEQ + qt * 64 + r) * NHEAD + h) * HDIM + c];
    }

    float m[4], l[4], acc[4][4];
    #pragma unroll
    for (int i = 0; i < 4; i++) {
        m[i] = -1e30f; l[i] = 0.f;
        #pragma unroll
        for (int j = 0; j < 4; j++) acc[i][j] = 0.f;
    }

    for (int kt = 0; kt <= qt; kt++) {
        __syncthreads();   // protect Ks/Vs/Ps reuse (and first-iter Qs visibility)
        // load K/V tiles (float4, KV shared across all heads -> L2 hits)
        for (int i = tid * 4; i < 64 * 64; i += 256 * 4) {
            int r = i >> 6, c = i & 63;
            float4 k4 = *(const float4*)(Kg + ((size_t)b * SEQ + kt * 64 + r) * HDIM + c);
            Ks[r * 65 + c + 0] = k4.x; Ks[r * 65 + c + 1] = k4.y;
            Ks[r * 65 + c + 2] = k4.z; Ks[r * 65 + c + 3] = k4.w;
            float4 v4 = *(const float4*)(Vg + ((size_t)b * SEQ + kt * 64 + r) * HDIM + c);
            *(float4*)(Vs + r * 64 + c) = v4;
        }
        __syncthreads();

        // S = Q K^T  (4x4 per thread)
        float s[4][4];
        #pragma unroll
        for (int i = 0; i < 4; i++)
            #pragma unroll
            for (int j = 0; j < 4; j++) s[i][j] = 0.f;

        #pragma unroll 4
        for (int k = 0; k < 64; k++) {
            float rq[4], rk[4];
            #pragma unroll
            for (int i = 0; i < 4; i++) rq[i] = Qs[(ty * 4 + i) * 64 + k];
            #pragma unroll
            for (int j = 0; j < 4; j++) rk[j] = Ks[(tx * 4 + j) * 65 + k];
            #pragma unroll
            for (int i = 0; i < 4; i++)
                #pragma unroll
                for (int j = 0; j < 4; j++)
                    s[i][j] = fmaf(rq[i], rk[j], s[i][j]);
        }

        const bool diag = (kt == qt);
        #pragma unroll
        for (int i = 0; i < 4; i++) {
            #pragma unroll
            for (int j = 0; j < 4; j++) {
                s[i][j] *= scale;
                if (diag && (kt * 64 + tx * 4 + j) > (qt * 64 + ty * 4 + i))
                    s[i][j] = -1e30f;
            }
        }

        // online softmax: row stats across the 16 tx threads (width-16 shfl)
        #pragma unroll
        for (int i = 0; i < 4; i++) {
            float rmax = s[i][0];
            #pragma unroll
            for (int j = 1; j < 4; j++) rmax = fmaxf(rmax, s[i][j]);
            #pragma unroll
            for (int off = 8; off >= 1; off >>= 1)
                rmax = fmaxf(rmax, __shfl_xor_sync(0xffffffffu, rmax, off, 16));

            float mnew = fmaxf(m[i], rmax);
            float corr = __expf(m[i] - mnew);
            float rsum = 0.f;
            #pragma unroll
            for (int j = 0; j < 4; j++) {
                s[i][j] = __expf(s[i][j] - mnew);
                rsum += s[i][j];
            }
            #pragma unroll
            for (int off = 8; off >= 1; off >>= 1)
                rsum += __shfl_xor_sync(0xffffffffu, rsum, off, 16);

            l[i] = l[i] * corr + rsum;
            m[i] = mnew;
            #pragma unroll
            for (int j = 0; j < 4; j++) {
                acc[i][j] *= corr;
                Ps[(ty * 4 + i) * 64 + tx * 4 + j] = s[i][j];
            }
        }
        __syncthreads();

        // acc += P @ V
        #pragma unroll 4
        for (int t = 0; t < 64; t++) {
            float rp[4], rv[4];
            #pragma unroll
            for (int i = 0; i < 4; i++) rp[i] = Ps[(ty * 4 + i) * 64 + t];
            #pragma unroll
            for (int j = 0; j < 4; j++) rv[j] = Vs[t * 64 + tx * 4 + j];
            #pragma unroll
            for (int i = 0; i < 4; i++)
                #pragma unroll
                for (int j = 0; j < 4; j++)
                    acc[i][j] = fmaf(rp[i], rv[j], acc[i][j]);
        }
    }

    // write O [T][H*D]
    #pragma unroll
    for (int i = 0; i < 4; i++) {
        float inv = 1.f / l[i];
        #pragma unroll
        for (int j = 0; j < 4; j++) {
            O[((size_t)b * SEQ + qt * 64 + ty * 4 + i) * HID + h * HDIM + tx * 4 + j]
                = acc[i][j] * inv;
        }
    }
}

// ---------------------------------------------------------------------------
extern "C" void kernel_launch(void* const* d_in, const int* in_sizes, int n_in,
                              void* d_out, int out_size)
{
    const float* hs     = (const float*)d_in[0];
    const float* cosb   = (const float*)d_in[1];
    const float* sinb   = (const float*)d_in[2];
    const float* wqkv   = (const float*)d_in[3];
    const float* wdense = (const float*)d_in[4];
    float* out = (float*)d_out;

    float *p_qkv, *p_q, *p_k, *p_v, *p_attn;
    cudaGetSymbolAddress((void**)&p_qkv,  g_qkv);
    cudaGetSymbolAddress((void**)&p_q,    g_q);
    cudaGetSymbolAddress((void**)&p_k,    g_k);
    cudaGetSymbolAddress((void**)&p_v,    g_v);
    cudaGetSymbolAddress((void**)&p_attn, g_attn);

    const int FA_SMEM = (64 * 64 * 3 + 64 * 65) * (int)sizeof(float);  // 65792 B
    cudaFuncSetAttribute(flash_attn_kernel,
                         cudaFuncAttributeMaxDynamicSharedMemorySize, FA_SMEM);

    // 1) QKV projection: [4096,2176] = hs[4096,2048] @ wqkv[2176,2048]^T
    {
        dim3 grid(QKV_N / 128, T_TOK / 128);
        sgemm_nt_kernel<<<grid, 256>>>(hs, wqkv, p_qkv, T_TOK, QKV_N, HID);
    }
    // 2) RoPE + split
    rope_split_kernel<<<T_TOK, 256>>>(p_qkv, cosb, sinb, p_q, p_k, p_v);

    // 3) causal flash attention
    {
        dim3 grid(SEQ / 64, NHEAD, BATCH);
        flash_attn_kernel<<<grid, 256, FA_SMEM>>>(p_q, p_k, p_v, p_attn);
    }
    // 4) dense projection: out[4096,2048] = attn @ wdense[2048,2048]^T
    {
        dim3 grid(HID / 128, T_TOK / 128);
        sgemm_nt_kernel<<<grid, 256>>>(p_attn, wdense, out, T_TOK, HID, HID);
    }
}

// round 3
// speedup vs baseline: 2.9439x; 2.9439x over previous
#include <cuda_runtime.h>
#include <cuda_bf16.h>
#include <cstdint>
#include <math.h>

#define T_TOK 4096
#define BATCH 2
#define SEQ   2048
#define NHEAD 32
#define HDIM  64
#define HID   2048
#define QKV_N 2176
#define ROPE_HALF 32

// ---------------- scratch (device globals; no allocation allowed) ----------
__device__ float g_qkv [T_TOK * QKV_N];
__device__ float g_q   [T_TOK * HID];
__device__ float g_k   [T_TOK * HDIM];
__device__ float g_v   [T_TOK * HDIM];
__device__ float g_attn[T_TOK * HID];

// ---------------- tf32 mma helpers -----------------------------------------
__device__ __forceinline__ uint32_t f2tf(float x) {
    uint32_t r;
    asm("cvt.rna.tf32.f32 %0, %1;" : "=r"(r) : "f"(x));
    return r;
}

__device__ __forceinline__ void mma_tf32(float* c,
    uint32_t a0, uint32_t a1, uint32_t a2, uint32_t a3,
    uint32_t b0, uint32_t b1)
{
    asm volatile(
        "mma.sync.aligned.m16n8k8.row.col.f32.tf32.tf32.f32 "
        "{%0,%1,%2,%3}, {%4,%5,%6,%7}, {%8,%9}, {%0,%1,%2,%3};"
        : "+f"(c[0]), "+f"(c[1]), "+f"(c[2]), "+f"(c[3])
        : "r"(a0), "r"(a1), "r"(a2), "r"(a3), "r"(b0), "r"(b1));
}

__device__ __forceinline__ void cp_async16(uint32_t dst, const void* src) {
    asm volatile("cp.async.cg.shared.global [%0], [%1], 16;" :: "r"(dst), "l"(src));
}

// ---------------------------------------------------------------------------
// TF32 tensor-core GEMM:  C[m][n] = sum_k A[m][k]*B[n][k]   (NT)
// BM=BN=128, BK=32, 256 threads (8 warps, 2x4), warp tile 64x32,
// cp.async double-buffered. Padded smem stride 36 -> conflict-free frag loads.
// ---------------------------------------------------------------------------
#define GEMM_SMEM (2 * 2 * 128 * 36 * 4)

__global__ __launch_bounds__(256) void gemm_tf32_nt(
    const float* __restrict__ A, const float* __restrict__ B,
    float* __restrict__ C, int M, int N, int K)
{
    extern __shared__ float sm[];
    float* As = sm;                  // 2 stages x [128][36]
    float* Bs = sm + 2 * 128 * 36;

    const int tid  = threadIdx.x;
    const int lane = tid & 31, warp = tid >> 5;
    const int g  = lane >> 2, tg = lane & 3;
    const int wm = warp >> 2, wn = warp & 3;     // 2 x 4 warp grid
    const int bm = blockIdx.y * 128, bn = blockIdx.x * 128;

    const uint32_t as_base = (uint32_t)__cvta_generic_to_shared(As);
    const uint32_t bs_base = (uint32_t)__cvta_generic_to_shared(Bs);

    auto prefetch = [&](int stage, int k0) {
        #pragma unroll
        for (int l = 0; l < 4; l++) {
            int idx = l * 256 + tid;
            int row = idx >> 3, c4 = (idx & 7) * 4;
            cp_async16(as_base + (uint32_t)(stage * 128 * 36 + row * 36 + c4) * 4,
                       A + (size_t)(bm + row) * K + k0 + c4);
            cp_async16(bs_base + (uint32_t)(stage * 128 * 36 + row * 36 + c4) * 4,
                       B + (size_t)(bn + row) * K + k0 + c4);
        }
        asm volatile("cp.async.commit_group;");
    };

    float acc[4][4][4];
    #pragma unroll
    for (int i = 0; i < 4; i++)
        #pragma unroll
        for (int j = 0; j < 4; j++)
            #pragma unroll
            for (int r = 0; r < 4; r++) acc[i][j][r] = 0.f;

    const int nK = K / 32;
    prefetch(0, 0);

    for (int kt = 0; kt < nK; kt++) {
        int s = kt & 1;
        if (kt + 1 < nK) {
            prefetch(s ^ 1, (kt + 1) * 32);
            asm volatile("cp.async.wait_group 1;");
        } else {
            asm volatile("cp.async.wait_group 0;");
        }
        __syncthreads();

        const float* as = As + s * 128 * 36;
        const float* bs = Bs + s * 128 * 36;

        #pragma unroll
        for (int kk = 0; kk < 4; kk++) {
            uint32_t af[4][4], bf[4][2];
            const int c = kk * 8;
            #pragma unroll
            for (int mi = 0; mi < 4; mi++) {
                int r = wm * 64 + mi * 16;
                af[mi][0] = f2tf(as[(r + g    ) * 36 + c + tg    ]);
                af[mi][1] = f2tf(as[(r + g + 8) * 36 + c + tg    ]);
                af[mi][2] = f2tf(as[(r + g    ) * 36 + c + tg + 4]);
                af[mi][3] = f2tf(as[(r + g + 8) * 36 + c + tg + 4]);
            }
            #pragma unroll
            for (int ni = 0; ni < 4; ni++) {
                int r = wn * 32 + ni * 8;
                bf[ni][0] = f2tf(bs[(r + g) * 36 + c + tg    ]);
                bf[ni][1] = f2tf(bs[(r + g) * 36 + c + tg + 4]);
            }
            #pragma unroll
            for (int mi = 0; mi < 4; mi++)
                #pragma unroll
                for (int ni = 0; ni < 4; ni++)
                    mma_tf32(acc[mi][ni], af[mi][0], af[mi][1], af[mi][2], af[mi][3],
                             bf[ni][0], bf[ni][1]);
        }
        __syncthreads();
    }

    // epilogue: float2 stores
    #pragma unroll
    for (int mi = 0; mi < 4; mi++) {
        size_t r0 = (size_t)(bm + wm * 64 + mi * 16 + g);
        #pragma unroll
        for (int ni = 0; ni < 4; ni++) {
            int c = bn + wn * 32 + ni * 8 + tg * 2;
            *(float2*)(C + r0 * N + c)       = make_float2(acc[mi][ni][0], acc[mi][ni][1]);
            *(float2*)(C + (r0 + 8) * N + c) = make_float2(acc[mi][ni][2], acc[mi][ni][3]);
        }
    }
}

// ---------------------------------------------------------------------------
// RoPE + split
// ---------------------------------------------------------------------------
__global__ __launch_bounds__(256) void rope_split_kernel(
    const float* __restrict__ qkv,
    const float* __restrict__ cosb, const float* __restrict__ sinb,
    float* __restrict__ q, float* __restrict__ k, float* __restrict__ v)
{
    const int t = blockIdx.x;
    const float* row = qkv + (size_t)t * QKV_N;
    const float* cs  = cosb + t * ROPE_HALF;
    const float* sn  = sinb + t * ROPE_HALF;

    for (int i = threadIdx.x; i < NHEAD * ROPE_HALF; i += blockDim.x) {
        int hh = i >> 5, d = i & 31;
        float c = cs[d], s = sn[d];
        float x1 = row[hh * HDIM + d];
        float x2 = row[hh * HDIM + d + ROPE_HALF];
        q[(size_t)t * HID + hh * HDIM + d]             = x1 * c - x2 * s;
        q[(size_t)t * HID + hh * HDIM + d + ROPE_HALF] = x2 * c + x1 * s;
    }
    for (int i = threadIdx.x; i < ROPE_HALF; i += blockDim.x) {
        float c = cs[i], s = sn[i];
        float x1 = row[HID + i];
        float x2 = row[HID + i + ROPE_HALF];
        k[(size_t)t * HDIM + i]             = x1 * c - x2 * s;
        k[(size_t)t * HDIM + i + ROPE_HALF] = x2 * c + x1 * s;
    }
    for (int i = threadIdx.x; i < HDIM; i += blockDim.x) {
        v[(size_t)t * HDIM + i] = row[HID + HDIM + i];
    }
}

// ---------------------------------------------------------------------------
// Causal flash attention with tf32 mma. GQA, 1 KV head.
// grid = (S/64, NHEAD, BATCH), 128 threads (4 warps), warp owns 16 q-rows.
// smem: Ks[64][68], Vs[64][68], QP[64][68] (Q staging, then per-warp P).
// ---------------------------------------------------------------------------
#define FA_SMEM (3 * 64 * 68 * 4)

__global__ __launch_bounds__(128) void flash_tf32(
    const float* __restrict__ Q, const float* __restrict__ Kg,
    const float* __restrict__ Vg, float* __restrict__ O)
{
    extern __shared__ float sm[];
    float* Ks = sm;                 // [64][68]
    float* Vs = sm + 64 * 68;
    float* QP = sm + 2 * 64 * 68;   // Q staging, then P per warp

    const int tid  = threadIdx.x;
    const int lane = tid & 31, warp = tid >> 5;
    const int g = lane >> 2, tg = lane & 3;
    const int qt = blockIdx.x, h = blockIdx.y, b = blockIdx.z;
    const float scale = 0.125f;

    // stage Q tile (tf32-rounded)
    for (int i = tid * 4; i < 64 * 64; i += 128 * 4) {
        int r = i >> 6, c = i & 63;
        float4 q4 = *(const float4*)(Q + ((size_t)(b * SEQ + qt * 64 + r) * NHEAD + h) * HDIM + c);
        uint4 u;
        u.x = f2tf(q4.x); u.y = f2tf(q4.y); u.z = f2tf(q4.z); u.w = f2tf(q4.w);
        *(uint4*)(QP + r * 68 + c) = u;
    }
    __syncthreads();

    // Q fragments in registers (invariant across KV tiles)
    uint32_t qf[8][4];
    {
        const float* qs = QP + warp * 16 * 68;
        #pragma unroll
        for (int kk = 0; kk < 8; kk++) {
            qf[kk][0] = __float_as_uint(qs[(g    ) * 68 + kk * 8 + tg    ]);
            qf[kk][1] = __float_as_uint(qs[(g + 8) * 68 + kk * 8 + tg    ]);
            qf[kk][2] = __float_as_uint(qs[(g    ) * 68 + kk * 8 + tg + 4]);
            qf[kk][3] = __float_as_uint(qs[(g + 8) * 68 + kk * 8 + tg + 4]);
        }
    }

    float oacc[8][4];
    #pragma unroll
    for (int d = 0; d < 8; d++)
        #pragma unroll
        for (int r = 0; r < 4; r++) oacc[d][r] = 0.f;
    float mrow[2] = {-1e30f, -1e30f};
    float lrow[2] = {0.f, 0.f};

    for (int kt = 0; kt <= qt; kt++) {
        __syncthreads();   // previous Ks/Vs/QP reads done
        for (int i = tid * 4; i < 64 * 64; i += 128 * 4) {
            int r = i >> 6, c = i & 63;
            float4 k4 = *(const float4*)(Kg + (size_t)(b * SEQ + kt * 64 + r) * HDIM + c);
            uint4 ku;
            ku.x = f2tf(k4.x); ku.y = f2tf(k4.y); ku.z = f2tf(k4.z); ku.w = f2tf(k4.w);
            *(uint4*)(Ks + r * 68 + c) = ku;
            float4 v4 = *(const float4*)(Vg + (size_t)(b * SEQ + kt * 64 + r) * HDIM + c);
            uint4 vu;
            vu.x = f2tf(v4.x); vu.y = f2tf(v4.y); vu.z = f2tf(v4.z); vu.w = f2tf(v4.w);
            *(uint4*)(Vs + r * 68 + c) = vu;
        }
        __syncthreads();

        // S = Q K^T  (warp: 16 x 64)
        float sacc[8][4];
        #pragma unroll
        for (int ni = 0; ni < 8; ni++)
            #pragma unroll
            for (int r = 0; r < 4; r++) sacc[ni][r] = 0.f;

        #pragma unroll
        for (int kk = 0; kk < 8; kk++) {
            #pragma unroll
            for (int ni = 0; ni < 8; ni++) {
                uint32_t b0 = __float_as_uint(Ks[(ni * 8 + g) * 68 + kk * 8 + tg    ]);
                uint32_t b1 = __float_as_uint(Ks[(ni * 8 + g) * 68 + kk * 8 + tg + 4]);
                mma_tf32(sacc[ni], qf[kk][0], qf[kk][1], qf[kk][2], qf[kk][3], b0, b1);
            }
        }

        // softmax (2 rows per thread: g and g+8)
        const bool diag = (kt == qt);
        const int rloc[2] = {warp * 16 + g, warp * 16 + g + 8};
        #pragma unroll
        for (int rr = 0; rr < 2; rr++) {
            float mx = -1e30f;
            #pragma unroll
            for (int ni = 0; ni < 8; ni++) {
                float v0 = sacc[ni][rr * 2 + 0] * scale;
                float v1 = sacc[ni][rr * 2 + 1] * scale;
                if (diag) {
                    int c0 = ni * 8 + tg * 2;
                    if (c0     > rloc[rr]) v0 = -1e30f;
                    if (c0 + 1 > rloc[rr]) v1 = -1e30f;
                }
                sacc[ni][rr * 2 + 0] = v0;
                sacc[ni][rr * 2 + 1] = v1;
                mx = fmaxf(mx, fmaxf(v0, v1));
            }
            mx = fmaxf(mx, __shfl_xor_sync(0xffffffffu, mx, 1));
            mx = fmaxf(mx, __shfl_xor_sync(0xffffffffu, mx, 2));
            float mnew = fmaxf(mrow[rr], mx);
            float corr = __expf(mrow[rr] - mnew);
            float sum = 0.f;
            #pragma unroll
            for (int ni = 0; ni < 8; ni++) {
                float e0 = __expf(sacc[ni][rr * 2 + 0] - mnew);
                float e1 = __expf(sacc[ni][rr * 2 + 1] - mnew);
                sacc[ni][rr * 2 + 0] = e0;
                sacc[ni][rr * 2 + 1] = e1;
                sum += e0 + e1;
            }
            sum += __shfl_xor_sync(0xffffffffu, sum, 1);
            sum += __shfl_xor_sync(0xffffffffu, sum, 2);
            lrow[rr] = lrow[rr] * corr + sum;
            mrow[rr] = mnew;
            #pragma unroll
            for (int di = 0; di < 8; di++) {
                oacc[di][rr * 2 + 0] *= corr;
                oacc[di][rr * 2 + 1] *= corr;
            }
        }

        // P -> per-warp smem (tf32), re-fragment as A operand
        float* ps = QP + warp * 16 * 68;
        #pragma unroll
        for (int ni = 0; ni < 8; ni++) {
            uint32_t p0 = f2tf(sacc[ni][0]), p1 = f2tf(sacc[ni][1]);
            uint32_t p2 = f2tf(sacc[ni][2]), p3 = f2tf(sacc[ni][3]);
            *(float2*)(ps + (g    ) * 68 + ni * 8 + tg * 2) =
                make_float2(__uint_as_float(p0), __uint_as_float(p1));
            *(float2*)(ps + (g + 8) * 68 + ni * 8 + tg * 2) =
                make_float2(__uint_as_float(p2), __uint_as_float(p3));
        }
        __syncwarp();

        // O += P @ V
        #pragma unroll
        for (int kk = 0; kk < 8; kk++) {
            uint32_t a0 = __float_as_uint(ps[(g    ) * 68 + kk * 8 + tg    ]);
            uint32_t a1 = __float_as_uint(ps[(g + 8) * 68 + kk * 8 + tg    ]);
            uint32_t a2 = __float_as_uint(ps[(g    ) * 68 + kk * 8 + tg + 4]);
            uint32_t a3 = __float_as_uint(ps[(g + 8) * 68 + kk * 8 + tg + 4]);
            #pragma unroll
            for (int di = 0; di < 8; di++) {
                uint32_t b0 = __float_as_uint(Vs[(kk * 8 + tg    ) * 68 + di * 8 + g]);
                uint32_t b1 = __float_as_uint(Vs[(kk * 8 + tg + 4) * 68 + di * 8 + g]);
                mma_tf32(oacc[di], a0, a1, a2, a3, b0, b1);
            }
        }
    }

    // write O
    float inv0 = 1.f / lrow[0], inv1 = 1.f / lrow[1];
    size_t row0 = (size_t)(b * SEQ + qt * 64 + warp * 16 + g);
    size_t row1 = row0 + 8;
    #pragma unroll
    for (int di = 0; di < 8; di++) {
        int c = h * 64 + di * 8 + tg * 2;
        *(float2*)(O + row0 * HID + c) = make_float2(oacc[di][0] * inv0, oacc[di][1] * inv0);
        *(float2*)(O + row1 * HID + c) = make_float2(oacc[di][2] * inv1, oacc[di][3] * inv1);
    }
}

// ---------------------------------------------------------------------------
extern "C" void kernel_launch(void* const* d_in, const int* in_sizes, int n_in,
                              void* d_out, int out_size)
{
    const float* hs     = (const float*)d_in[0];
    const float* cosb   = (const float*)d_in[1];
    const float* sinb   = (const float*)d_in[2];
    const float* wqkv   = (const float*)d_in[3];
    const float* wdense = (const float*)d_in[4];
    float* out = (float*)d_out;

    float *p_qkv, *p_q, *p_k, *p_v, *p_attn;
    cudaGetSymbolAddress((void**)&p_qkv,  g_qkv);
    cudaGetSymbolAddress((void**)&p_q,    g_q);
    cudaGetSymbolAddress((void**)&p_k,    g_k);
    cudaGetSymbolAddress((void**)&p_v,    g_v);
    cudaGetSymbolAddress((void**)&p_attn, g_attn);

    cudaFuncSetAttribute(gemm_tf32_nt,
                         cudaFuncAttributeMaxDynamicSharedMemorySize, GEMM_SMEM);
    cudaFuncSetAttribute(flash_tf32,
                         cudaFuncAttributeMaxDynamicSharedMemorySize, FA_SMEM);

    // 1) QKV projection: [4096,2176] = hs @ wqkv^T
    {
        dim3 grid(QKV_N / 128, T_TOK / 128);
        gemm_tf32_nt<<<grid, 256, GEMM_SMEM>>>(hs, wqkv, p_qkv, T_TOK, QKV_N, HID);
    }
    // 2) RoPE + split
    rope_split_kernel<<<T_TOK, 256>>>(p_qkv, cosb, sinb, p_q, p_k, p_v);

    // 3) causal flash attention (tensor cores)
    {
        dim3 grid(SEQ / 64, NHEAD, BATCH);
        flash_tf32<<<grid, 128, FA_SMEM>>>(p_q, p_k, p_v, p_attn);
    }
    // 4) dense projection: out = attn @ wdense^T
    {
        dim3 grid(HID / 128, T_TOK / 128);
        gemm_tf32_nt<<<grid, 256, GEMM_SMEM>>>(p_attn, wdense, out, T_TOK, HID, HID);
    }
}

// round 4
// speedup vs baseline: 3.5349x; 1.2008x over previous
#include <cuda_runtime.h>
#include <cuda_bf16.h>
#include <cstdint>
#include <math.h>

#define T_TOK 4096
#define BATCH 2
#define SEQ   2048
#define NHEAD 32
#define HDIM  64
#define HID   2048
#define QKV_N 2176
#define ROPE_HALF 32

// ---------------- scratch (device globals; no allocation allowed) ----------
__device__ float g_qkv   [T_TOK * QKV_N];
__device__ float g_q     [T_TOK * HID];    // tf32-rounded
__device__ float g_k     [T_TOK * HDIM];   // tf32-rounded
__device__ float g_v     [T_TOK * HDIM];   // tf32-rounded
__device__ float g_attn  [T_TOK * HID];    // tf32-rounded
__device__ float g_hs    [T_TOK * HID];    // tf32-rounded copy of hidden_states
__device__ float g_wqkv  [QKV_N * HID];    // tf32-rounded copy of w_qkv
__device__ float g_wdense[HID * HID];      // tf32-rounded copy of w_dense

// ---------------- helpers ---------------------------------------------------
__device__ __forceinline__ uint32_t f2tf(float x) {
    uint32_t r;
    asm("cvt.rna.tf32.f32 %0, %1;" : "=r"(r) : "f"(x));
    return r;
}

__device__ __forceinline__ void mma_tf32(float* c,
    uint32_t a0, uint32_t a1, uint32_t a2, uint32_t a3,
    uint32_t b0, uint32_t b1)
{
    asm volatile(
        "mma.sync.aligned.m16n8k8.row.col.f32.tf32.tf32.f32 "
        "{%0,%1,%2,%3}, {%4,%5,%6,%7}, {%8,%9}, {%0,%1,%2,%3};"
        : "+f"(c[0]), "+f"(c[1]), "+f"(c[2]), "+f"(c[3])
        : "r"(a0), "r"(a1), "r"(a2), "r"(a3), "r"(b0), "r"(b1));
}

__device__ __forceinline__ void cp_async16(uint32_t dst, const void* src) {
    asm volatile("cp.async.cg.shared.global [%0], [%1], 16;" :: "r"(dst), "l"(src));
}

// ---------------------------------------------------------------------------
// tf32 pre-rounding pass (bandwidth bound, float4)
// ---------------------------------------------------------------------------
__global__ __launch_bounds__(256) void tf32_round_kernel(
    const float* __restrict__ src, float* __restrict__ dst, int n4)
{
    int i = blockIdx.x * blockDim.x + threadIdx.x;
    if (i < n4) {
        float4 v = ((const float4*)src)[i];
        uint4 u;
        u.x = f2tf(v.x); u.y = f2tf(v.y); u.z = f2tf(v.z); u.w = f2tf(v.w);
        ((uint4*)dst)[i] = u;
    }
}

// ---------------------------------------------------------------------------
// TF32 GEMM (NT): C[m][n] = sum_k A[m][k]*B[n][k]. Inputs pre-rounded to tf32.
// BM=BN=128, BK=32, 256 threads (2x4 warps), 2-stage cp.async, 2 CTAs/SM.
// ---------------------------------------------------------------------------
#define GEMM_SMEM (2 * 2 * 128 * 36 * 4)

__global__ __launch_bounds__(256, 2) void gemm_tf32_nt(
    const float* __restrict__ A, const float* __restrict__ B,
    float* __restrict__ C, int M, int N, int K)
{
    extern __shared__ float sm[];
    float* As = sm;                  // 2 stages x [128][36]
    float* Bs = sm + 2 * 128 * 36;

    const int tid  = threadIdx.x;
    const int lane = tid & 31, warp = tid >> 5;
    const int g  = lane >> 2, tg = lane & 3;
    const int wm = warp >> 2, wn = warp & 3;
    const int bm = blockIdx.y * 128, bn = blockIdx.x * 128;

    const uint32_t as_base = (uint32_t)__cvta_generic_to_shared(As);
    const uint32_t bs_base = (uint32_t)__cvta_generic_to_shared(Bs);

    auto prefetch = [&](int stage, int k0) {
        #pragma unroll
        for (int l = 0; l < 4; l++) {
            int idx = l * 256 + tid;
            int row = idx >> 3, c4 = (idx & 7) * 4;
            cp_async16(as_base + (uint32_t)(stage * 128 * 36 + row * 36 + c4) * 4,
                       A + (size_t)(bm + row) * K + k0 + c4);
            cp_async16(bs_base + (uint32_t)(stage * 128 * 36 + row * 36 + c4) * 4,
                       B + (size_t)(bn + row) * K + k0 + c4);
        }
        asm volatile("cp.async.commit_group;");
    };

    float acc[4][4][4];
    #pragma unroll
    for (int i = 0; i < 4; i++)
        #pragma unroll
        for (int j = 0; j < 4; j++)
            #pragma unroll
            for (int r = 0; r < 4; r++) acc[i][j][r] = 0.f;

    const int nK = K / 32;
    prefetch(0, 0);

    for (int kt = 0; kt < nK; kt++) {
        int s = kt & 1;
        if (kt + 1 < nK) {
            prefetch(s ^ 1, (kt + 1) * 32);
            asm volatile("cp.async.wait_group 1;");
        } else {
            asm volatile("cp.async.wait_group 0;");
        }
        __syncthreads();

        const float* as = As + s * 128 * 36;
        const float* bs = Bs + s * 128 * 36;

        #pragma unroll
        for (int kk = 0; kk < 4; kk++) {
            uint32_t af[4][4], bf[4][2];
            const int c = kk * 8;
            #pragma unroll
            for (int mi = 0; mi < 4; mi++) {
                int r = wm * 64 + mi * 16;
                af[mi][0] = __float_as_uint(as[(r + g    ) * 36 + c + tg    ]);
                af[mi][1] = __float_as_uint(as[(r + g + 8) * 36 + c + tg    ]);
                af[mi][2] = __float_as_uint(as[(r + g    ) * 36 + c + tg + 4]);
                af[mi][3] = __float_as_uint(as[(r + g + 8) * 36 + c + tg + 4]);
            }
            #pragma unroll
            for (int ni = 0; ni < 4; ni++) {
                int r = wn * 32 + ni * 8;
                bf[ni][0] = __float_as_uint(bs[(r + g) * 36 + c + tg    ]);
                bf[ni][1] = __float_as_uint(bs[(r + g) * 36 + c + tg + 4]);
            }
            #pragma unroll
            for (int mi = 0; mi < 4; mi++)
                #pragma unroll
                for (int ni = 0; ni < 4; ni++)
                    mma_tf32(acc[mi][ni], af[mi][0], af[mi][1], af[mi][2], af[mi][3],
                             bf[ni][0], bf[ni][1]);
        }
        __syncthreads();
    }

    #pragma unroll
    for (int mi = 0; mi < 4; mi++) {
        size_t r0 = (size_t)(bm + wm * 64 + mi * 16 + g);
        #pragma unroll
        for (int ni = 0; ni < 4; ni++) {
            int c = bn + wn * 32 + ni * 8 + tg * 2;
            *(float2*)(C + r0 * N + c)       = make_float2(acc[mi][ni][0], acc[mi][ni][1]);
            *(float2*)(C + (r0 + 8) * N + c) = make_float2(acc[mi][ni][2], acc[mi][ni][3]);
        }
    }
}

// ---------------------------------------------------------------------------
// RoPE + split. Emits tf32-rounded q, k, v.
// ---------------------------------------------------------------------------
__global__ __launch_bounds__(256) void rope_split_kernel(
    const float* __restrict__ qkv,
    const float* __restrict__ cosb, const float* __restrict__ sinb,
    float* __restrict__ q, float* __restrict__ k, float* __restrict__ v)
{
    const int t = blockIdx.x;
    const float* row = qkv + (size_t)t * QKV_N;
    const float* cs  = cosb + t * ROPE_HALF;
    const float* sn  = sinb + t * ROPE_HALF;

    for (int i = threadIdx.x; i < NHEAD * ROPE_HALF; i += blockDim.x) {
        int hh = i >> 5, d = i & 31;
        float c = cs[d], s = sn[d];
        float x1 = row[hh * HDIM + d];
        float x2 = row[hh * HDIM + d + ROPE_HALF];
        ((uint32_t*)q)[(size_t)t * HID + hh * HDIM + d]             = f2tf(x1 * c - x2 * s);
        ((uint32_t*)q)[(size_t)t * HID + hh * HDIM + d + ROPE_HALF] = f2tf(x2 * c + x1 * s);
    }
    for (int i = threadIdx.x; i < ROPE_HALF; i += blockDim.x) {
        float c = cs[i], s = sn[i];
        float x1 = row[HID + i];
        float x2 = row[HID + i + ROPE_HALF];
        ((uint32_t*)k)[(size_t)t * HDIM + i]             = f2tf(x1 * c - x2 * s);
        ((uint32_t*)k)[(size_t)t * HDIM + i + ROPE_HALF] = f2tf(x2 * c + x1 * s);
    }
    for (int i = threadIdx.x; i < HDIM; i += blockDim.x) {
        ((uint32_t*)v)[(size_t)t * HDIM + i] = f2tf(row[HID + HDIM + i]);
    }
}

// ---------------------------------------------------------------------------
// Causal flash attention v2. BM=128 (8 warps), BN=64, cp.async double-buffered
// KV, per-warp skip of fully-masked tiles. Inputs pre-rounded tf32.
// smem: Ks[2][64][68], Vs[2][64][68], QP[128][68].
// ---------------------------------------------------------------------------
#define KV_T   (64 * 68)
#define FA_SMEM ((4 * KV_T + 128 * 68) * 4)

__global__ __launch_bounds__(256, 2) void flash_tf32_v2(
    const float* __restrict__ Q, const float* __restrict__ Kg,
    const float* __restrict__ Vg, float* __restrict__ O)
{
    extern __shared__ float sm[];
    float* QP = sm + 4 * KV_T;

    const int tid  = threadIdx.x;
    const int lane = tid & 31, warp = tid >> 5;
    const int g = lane >> 2, tg = lane & 3;
    const int qt = blockIdx.x, h = blockIdx.y, b = blockIdx.z;
    const float scale = 0.125f;
    const int nkt = 2 * qt + 2;
    const int row_min = qt * 128 + warp * 16;

    const uint32_t sm_base = (uint32_t)__cvta_generic_to_shared(sm);
    const uint32_t qp_base = sm_base + 4 * KV_T * 4;

    // Q tile -> QP (group 0)
    for (int i = tid * 4; i < 128 * 64; i += 1024) {
        int r = i >> 6, c = i & 63;
        cp_async16(qp_base + (uint32_t)(r * 68 + c) * 4,
                   Q + ((size_t)(b * SEQ + qt * 128 + r) * NHEAD + h) * HDIM + c);
    }
    asm volatile("cp.async.commit_group;");

    auto prefetch_kv = [&](int s, int kt) {
        const float* kp = Kg + (size_t)(b * SEQ + kt * 64) * HDIM;
        const float* vp = Vg + (size_t)(b * SEQ + kt * 64) * HDIM;
        #pragma unroll
        for (int i = tid * 4; i < 64 * 64; i += 1024) {
            int r = i >> 6, c = i & 63;
            cp_async16(sm_base + (uint32_t)(s * KV_T + r * 68 + c) * 4, kp + r * 64 + c);
            cp_async16(sm_base + (uint32_t)((2 + s) * KV_T + r * 68 + c) * 4, vp + r * 64 + c);
        }
        asm volatile("cp.async.commit_group;");
    };

    prefetch_kv(0, 0);               // group 1
    prefetch_kv(1, 1);               // group 2 (nkt >= 2 always)

    asm volatile("cp.async.wait_group 2;");   // Q arrived
    __syncthreads();

    // Q fragments (invariant across KV tiles)
    uint32_t qf[8][4];
    {
        const float* qs = QP + warp * 16 * 68;
        #pragma unroll
        for (int kk = 0; kk < 8; kk++) {
            qf[kk][0] = __float_as_uint(qs[(g    ) * 68 + kk * 8 + tg    ]);
            qf[kk][1] = __float_as_uint(qs[(g + 8) * 68 + kk * 8 + tg    ]);
            qf[kk][2] = __float_as_uint(qs[(g    ) * 68 + kk * 8 + tg + 4]);
            qf[kk][3] = __float_as_uint(qs[(g + 8) * 68 + kk * 8 + tg + 4]);
        }
    }

    float oacc[8][4];
    #pragma unroll
    for (int d = 0; d < 8; d++)
        #pragma unroll
        for (int r = 0; r < 4; r++) oacc[d][r] = 0.f;
    float mrow[2] = {-1e30f, -1e30f};
    float lrow[2] = {0.f, 0.f};

    for (int kt = 0; kt < nkt; kt++) {
        const int s = kt & 1;
        if (kt + 1 < nkt) asm volatile("cp.async.wait_group 1;");
        else              asm volatile("cp.async.wait_group 0;");
        __syncthreads();

        const bool skip = (kt * 64) > (row_min + 15);
        if (!skip) {
            const float* ks = sm + s * KV_T;
            const float* vs = sm + (2 + s) * KV_T;

            // S = Q K^T  (warp: 16 x 64)
            float sacc[8][4];
            #pragma unroll
            for (int ni = 0; ni < 8; ni++)
                #pragma unroll
                for (int r = 0; r < 4; r++) sacc[ni][r] = 0.f;

            #pragma unroll
            for (int kk = 0; kk < 8; kk++) {
                #pragma unroll
                for (int ni = 0; ni < 8; ni++) {
                    uint32_t b0 = __float_as_uint(ks[(ni * 8 + g) * 68 + kk * 8 + tg    ]);
                    uint32_t b1 = __float_as_uint(ks[(ni * 8 + g) * 68 + kk * 8 + tg + 4]);
                    mma_tf32(sacc[ni], qf[kk][0], qf[kk][1], qf[kk][2], qf[kk][3], b0, b1);
                }
            }

            const bool need_mask = (kt * 64 + 63) > row_min;
            const int rloc[2] = {row_min + g, row_min + g + 8};

            #pragma unroll
            for (int rr = 0; rr < 2; rr++) {
                float mx = -1e30f;
                #pragma unroll
                for (int ni = 0; ni < 8; ni++) {
                    float v0 = sacc[ni][rr * 2 + 0] * scale;
                    float v1 = sacc[ni][rr * 2 + 1] * scale;
                    if (need_mask) {
                        int c0 = kt * 64 + ni * 8 + tg * 2;
                        if (c0     > rloc[rr]) v0 = -1e30f;
                        if (c0 + 1 > rloc[rr]) v1 = -1e30f;
                    }
                    sacc[ni][rr * 2 + 0] = v0;
                    sacc[ni][rr * 2 + 1] = v1;
                    mx = fmaxf(mx, fmaxf(v0, v1));
                }
                mx = fmaxf(mx, __shfl_xor_sync(0xffffffffu, mx, 1));
                mx = fmaxf(mx, __shfl_xor_sync(0xffffffffu, mx, 2));
                float mnew = fmaxf(mrow[rr], mx);
                float corr = __expf(mrow[rr] - mnew);
                float sum = 0.f;
                #pragma unroll
                for (int ni = 0; ni < 8; ni++) {
                    float e0 = __expf(sacc[ni][rr * 2 + 0] - mnew);
                    float e1 = __expf(sacc[ni][rr * 2 + 1] - mnew);
                    sacc[ni][rr * 2 + 0] = e0;
                    sacc[ni][rr * 2 + 1] = e1;
                    sum += e0 + e1;
                }
                sum += __shfl_xor_sync(0xffffffffu, sum, 1);
                sum += __shfl_xor_sync(0xffffffffu, sum, 2);
                lrow[rr] = lrow[rr] * corr + sum;
                mrow[rr] = mnew;
                #pragma unroll
                for (int di = 0; di < 8; di++) {
                    oacc[di][rr * 2 + 0] *= corr;
                    oacc[di][rr * 2 + 1] *= corr;
                }
            }

            // P -> per-warp smem (tf32), re-fragment as A operand
            float* ps = QP + warp * 16 * 68;
            #pragma unroll
            for (int ni = 0; ni < 8; ni++) {
                uint32_t p0 = f2tf(sacc[ni][0]), p1 = f2tf(sacc[ni][1]);
                uint32_t p2 = f2tf(sacc[ni][2]), p3 = f2tf(sacc[ni][3]);
                *(float2*)(ps + (g    ) * 68 + ni * 8 + tg * 2) =
                    make_float2(__uint_as_float(p0), __uint_as_float(p1));
                *(float2*)(ps + (g + 8) * 68 + ni * 8 + tg * 2) =
                    make_float2(__uint_as_float(p2), __uint_as_float(p3));
            }
            __syncwarp();

            // O += P @ V
            #pragma unroll
            for (int kk = 0; kk < 8; kk++) {
                uint32_t a0 = __float_as_uint(ps[(g    ) * 68 + kk * 8 + tg    ]);
                uint32_t a1 = __float_as_uint(ps[(g + 8) * 68 + kk * 8 + tg    ]);
                uint32_t a2 = __float_as_uint(ps[(g    ) * 68 + kk * 8 + tg + 4]);
                uint32_t a3 = __float_as_uint(ps[(g + 8) * 68 + kk * 8 + tg + 4]);
                #pragma unroll
                for (int di = 0; di < 8; di++) {
                    uint32_t b0 = __float_as_uint(vs[(kk * 8 + tg    ) * 68 + di * 8 + g]);
                    uint32_t b1 = __float_as_uint(vs[(kk * 8 + tg + 4) * 68 + di * 8 + g]);
                    mma_tf32(oacc[di], a0, a1, a2, a3, b0, b1);
                }
            }
        }

        __syncthreads();   // all reads of stage s done before refill
        if (kt + 2 < nkt) prefetch_kv(s, kt + 2);
    }

    // write O (tf32-rounded: it is the A operand of the dense GEMM)
    float inv0 = 1.f / lrow[0], inv1 = 1.f / lrow[1];
    size_t row0 = (size_t)(b * SEQ + qt * 128 + warp * 16 + g);
    size_t row1 = row0 + 8;
    #pragma unroll
    for (int di = 0; di < 8; di++) {
        int c = h * 64 + di * 8 + tg * 2;
        uint32_t o0 = f2tf(oacc[di][0] * inv0), o1 = f2tf(oacc[di][1] * inv0);
        uint32_t o2 = f2tf(oacc[di][2] * inv1), o3 = f2tf(oacc[di][3] * inv1);
        *(float2*)(O + row0 * HID + c) = make_float2(__uint_as_float(o0), __uint_as_float(o1));
        *(float2*)(O + row1 * HID + c) = make_float2(__uint_as_float(o2), __uint_as_float(o3));
    }
}

// ---------------------------------------------------------------------------
extern "C" void kernel_launch(void* const* d_in, const int* in_sizes, int n_in,
                              void* d_out, int out_size)
{
    const float* hs     = (const float*)d_in[0];
    const float* cosb   = (const float*)d_in[1];
    const float* sinb   = (const float*)d_in[2];
    const float* wqkv   = (const float*)d_in[3];
    const float* wdense = (const float*)d_in[4];
    float* out = (float*)d_out;

    float *p_qkv, *p_q, *p_k, *p_v, *p_attn, *p_hs, *p_wqkv, *p_wdense;
    cudaGetSymbolAddress((void**)&p_qkv,    g_qkv);
    cudaGetSymbolAddress((void**)&p_q,      g_q);
    cudaGetSymbolAddress((void**)&p_k,      g_k);
    cudaGetSymbolAddress((void**)&p_v,      g_v);
    cudaGetSymbolAddress((void**)&p_attn,   g_attn);
    cudaGetSymbolAddress((void**)&p_hs,     g_hs);
    cudaGetSymbolAddress((void**)&p_wqkv,   g_wqkv);
    cudaGetSymbolAddress((void**)&p_wdense, g_wdense);

    cudaFuncSetAttribute(gemm_tf32_nt,
                         cudaFuncAttributeMaxDynamicSharedMemorySize, GEMM_SMEM);
    cudaFuncSetAttribute(flash_tf32_v2,
                         cudaFuncAttributeMaxDynamicSharedMemorySize, FA_SMEM);

    // 0) pre-round inputs to tf32 (bandwidth bound)
    tf32_round_kernel<<<(T_TOK * HID / 4 + 255) / 256, 256>>>(hs, p_hs, T_TOK * HID / 4);
    tf32_round_kernel<<<(QKV_N * HID / 4 + 255) / 256, 256>>>(wqkv, p_wqkv, QKV_N * HID / 4);
    tf32_round_kernel<<<(HID * HID / 4 + 255) / 256, 256>>>(wdense, p_wdense, HID * HID / 4);

    // 1) QKV projection
    {
        dim3 grid(QKV_N / 128, T_TOK / 128);
        gemm_tf32_nt<<<grid, 256, GEMM_SMEM>>>(p_hs, p_wqkv, p_qkv, T_TOK, QKV_N, HID);
    }
    // 2) RoPE + split (emits tf32)
    rope_split_kernel<<<T_TOK, 256>>>(p_qkv, cosb, sinb, p_q, p_k, p_v);

    // 3) causal flash attention
    {
        dim3 grid(SEQ / 128, NHEAD, BATCH);
        flash_tf32_v2<<<grid, 256, FA_SMEM>>>(p_q, p_k, p_v, p_attn);
    }
    // 4) dense projection
    {
        dim3 grid(HID / 128, T_TOK / 128);
        gemm_tf32_nt<<<grid, 256, GEMM_SMEM>>>(p_attn, p_wdense, out, T_TOK, HID, HID);
    }
}